// round 16
// baseline (speedup 1.0000x reference)
#include <cuda_runtime.h>
#include <cuda_bf16.h>
#include <math.h>
#include <stdint.h>

#define NV 100000
#define NE 20000
#define CH 128
#define NCLS 40
#define BN_EPS 1e-5f
#define EPAD 256   // max hyperedge degree slot (mean 160, sigma 12.6)
#define VPAD 128   // max vertex degree slot (mean 32, sigma 5.7)

// ---------------- scratch (device globals; no cudaMalloc allowed) ----------------
__device__ static float g_ebuf [(size_t)NE * CH];           // 10.24 MB (agg1 out)
__device__ static float g_vbuf [(size_t)NV * CH];           // 51.2 MB (agg2 out)
__device__ static __nv_bfloat16 g_xh   [(size_t)NV * CH];   // 25.6 MB (x bf16)
__device__ static __nv_bfloat16 g_eh   [(size_t)NE * CH];   // 5.12 MB (fused gemm out -> agg2 src)
__device__ static __nv_bfloat16 g_vb2h [(size_t)NV * NCLS]; // 8 MB (gemm40 out -> agg3 src)
__device__ static __nv_bfloat16 g_e40h [(size_t)NE * NCLS]; // 1.6 MB (fused agg3 out -> agg4 src)
__device__ static int      g_ecnt[NE];
__device__ static int      g_vcnt[NV];
__device__ static int      g_eadj[(size_t)NE * EPAD];       // 20.48 MB (v ids, 32-bit)
__device__ static uint16_t g_vadj16[(size_t)NV * VPAD];     // 25.6 MB (e ids < 20000 -> u16)

// ---------------- prelude: x->bf16 convert fused with count zeroing ----------------
__global__ void cvt_zero(const float* __restrict__ src, __nv_bfloat16* __restrict__ dst, int n,
                         int* ecnt, int* vcnt) {
    int t = blockIdx.x * blockDim.x + threadIdx.x;
    int i = t * 4;
    if (i < n) {
        float4 f = *reinterpret_cast<const float4*>(src + i);
        __nv_bfloat162 a = __floats2bfloat162_rn(f.x, f.y);
        __nv_bfloat162 b = __floats2bfloat162_rn(f.z, f.w);
        uint2 o;
        o.x = *reinterpret_cast<uint32_t*>(&a);
        o.y = *reinterpret_cast<uint32_t*>(&b);
        *reinterpret_cast<uint2*>(dst + i) = o;
    }
    if (t < NE) ecnt[t] = 0;
    int u = t - NE;
    if (u >= 0 && u < NV) vcnt[u] = 0;
}

// Single-pass padded adjacency build (rank = atomic return value). vadj stored u16.
__global__ void build_padded(const int* __restrict__ v_ids, const int* __restrict__ e_ids,
                             int* ecnt, int* vcnt,
                             int* __restrict__ eadj, uint16_t* __restrict__ vadj, int nnz) {
    for (int i = blockIdx.x * blockDim.x + threadIdx.x; i < nnz; i += gridDim.x * blockDim.x) {
        int e = e_ids[i], v = v_ids[i];
        int re = atomicAdd(&ecnt[e], 1);
        if (re < EPAD) eadj[((size_t)e << 8) + re] = v;
        int rv = atomicAdd(&vcnt[v], 1);
        if (rv < VPAD) vadj[((size_t)v << 7) + rv] = (uint16_t)e;
    }
}

// bf16x2 word -> packed f32x2 (exact: bf16->f32 is a left shift by 16)
__device__ __forceinline__ uint64_t bf16x2_to_f32x2(uint32_t w) {
    uint32_t lo = w << 16;
    uint32_t hi = w & 0xffff0000u;
    uint64_t r;
    asm("mov.b64 %0, {%1, %2};" : "=l"(r) : "r"(lo), "r"(hi));
    return r;
}

__device__ __forceinline__ void acc2_bf16x8(uint64_t* acc2, uint4 p) {
    const uint32_t* w = &p.x;
    #pragma unroll
    for (int q = 0; q < 4; q++) {
        uint64_t f2 = bf16x2_to_f32x2(w[q]);
        asm("add.rn.f32x2 %0, %0, %1;" : "+l"(acc2[q]) : "l"(f2));
    }
}

__device__ __forceinline__ void acc_bf16x8(float* acc, uint4 p) {
    const uint32_t* w = &p.x;
    #pragma unroll
    for (int q = 0; q < 4; q++) {
        float2 f = __bfloat1622float2(*reinterpret_cast<const __nv_bfloat162*>(&w[q]));
        acc[q * 2 + 0] += f.x;
        acc[q * 2 + 1] += f.y;
    }
}

__device__ __forceinline__ void acc_bf16x4(float* acc, uint2 p) {
    const uint32_t* w = &p.x;
    #pragma unroll
    for (int q = 0; q < 2; q++) {
        float2 f = __bfloat1622float2(*reinterpret_cast<const __nv_bfloat162*>(&w[q]));
        acc[q * 2 + 0] += f.x;
        acc[q * 2 + 1] += f.y;
    }
}

// ---------------- agg1: e-side segment mean, bf16 source, 128 ch, f32x2 accumulate ----------------
__global__ void __launch_bounds__(128)
seg_agg_h128(const __nv_bfloat16* __restrict__ src, const int* __restrict__ cnt,
             const int* __restrict__ adj, float* __restrict__ dst, int nseg) {
    const int tid = threadIdx.x;
    const int chunk = tid % 16;
    const int rl = tid / 16;
    __shared__ float sacc[8][16][8];

    for (int s = blockIdx.x; s < nseg; s += gridDim.x) {
        int deg = cnt[s]; if (deg > EPAD) deg = EPAD;
        const size_t base = (size_t)s << 8;
        uint64_t acc2[4];
        #pragma unroll
        for (int q = 0; q < 4; q++) acc2[q] = 0ull;

        int j = rl;
        for (; j + 24 < deg; j += 32) {
            int i0 = adj[base + j],      i1 = adj[base + j + 8];
            int i2 = adj[base + j + 16], i3 = adj[base + j + 24];
            uint4 p0 = *reinterpret_cast<const uint4*>(src + (size_t)i0 * 128 + chunk * 8);
            uint4 p1 = *reinterpret_cast<const uint4*>(src + (size_t)i1 * 128 + chunk * 8);
            uint4 p2 = *reinterpret_cast<const uint4*>(src + (size_t)i2 * 128 + chunk * 8);
            uint4 p3 = *reinterpret_cast<const uint4*>(src + (size_t)i3 * 128 + chunk * 8);
            acc2_bf16x8(acc2, p0);
            acc2_bf16x8(acc2, p1);
            acc2_bf16x8(acc2, p2);
            acc2_bf16x8(acc2, p3);
        }
        for (; j < deg; j += 8) {
            int i0 = adj[base + j];
            uint4 p0 = *reinterpret_cast<const uint4*>(src + (size_t)i0 * 128 + chunk * 8);
            acc2_bf16x8(acc2, p0);
        }
        float accf[8];
        #pragma unroll
        for (int q = 0; q < 4; q++) {
            uint32_t lo, hi;
            asm("mov.b64 {%0, %1}, %2;" : "=r"(lo), "=r"(hi) : "l"(acc2[q]));
            accf[q * 2 + 0] = __uint_as_float(lo);
            accf[q * 2 + 1] = __uint_as_float(hi);
        }
        #pragma unroll
        for (int k = 0; k < 8; k++) sacc[rl][chunk][k] = accf[k];
        __syncthreads();
        if (rl == 0) {
            #pragma unroll
            for (int r = 1; r < 8; r++)
                #pragma unroll
                for (int k = 0; k < 8; k++) accf[k] += sacc[r][chunk][k];
            float inv = 1.0f / (float)(deg < 1 ? 1 : deg);
            #pragma unroll
            for (int k = 0; k < 8; k++) accf[k] *= inv;
            float4 o0 = make_float4(accf[0], accf[1], accf[2], accf[3]);
            float4 o1 = make_float4(accf[4], accf[5], accf[6], accf[7]);
            *reinterpret_cast<float4*>(dst + (size_t)s * 128 + chunk * 8) = o0;
            *reinterpret_cast<float4*>(dst + (size_t)s * 128 + chunk * 8 + 4) = o1;
        }
        __syncthreads();
    }
}

// ---------------- fused layer-1 GEMM pair: Out_bf16 = relu(A@W1) @ W2 ----------------
// 32-row tiles: grid 313 -> 625 CTAs (the real occupancy binder was launch width,
// not smem/regs: 313 CTAs / 148 SMs = 2.1). 18 KB smem, ~50 regs -> 4+ CTAs/SM.
__global__ void __launch_bounds__(256)
gemm128_fused(const float* __restrict__ A, const float* __restrict__ W1,
              const float* __restrict__ W2, __nv_bfloat16* __restrict__ Out, int M) {
    __shared__ float As[32][16];
    __shared__ __align__(16) float Ws[16][128];
    __shared__ __align__(16) __nv_bfloat16 Ts[32][128];
    const int tid = threadIdx.x;
    const int c4 = tid % 32;
    const int rg = tid / 32;          // 0..7, each handles 4 rows
    const int row0 = blockIdx.x * 32;
    float4 acc[4];
    #pragma unroll
    for (int i = 0; i < 4; i++) acc[i] = make_float4(0.f, 0.f, 0.f, 0.f);

    // ---- phase 1: T = relu(A @ W1) ----
    for (int k0 = 0; k0 < 128; k0 += 16) {
        if (tid < 128) {
            int r = tid >> 2, cc = (tid & 3) * 4;
            int gr = row0 + r;
            float4 v = make_float4(0.f, 0.f, 0.f, 0.f);
            if (gr < M) v = *reinterpret_cast<const float4*>(A + (size_t)gr * 128 + k0 + cc);
            *reinterpret_cast<float4*>(&As[r][cc]) = v;
        }
        #pragma unroll
        for (int w = 0; w < 2; w++) {
            int idx = tid + w * 256;
            int kr = idx >> 5, cc = (idx & 31) * 4;
            *reinterpret_cast<float4*>(&Ws[kr][cc]) =
                *reinterpret_cast<const float4*>(W1 + (size_t)(k0 + kr) * 128 + cc);
        }
        __syncthreads();
        #pragma unroll
        for (int kk = 0; kk < 16; kk++) {
            float4 bv = *reinterpret_cast<const float4*>(&Ws[kk][c4 * 4]);
            #pragma unroll
            for (int i = 0; i < 4; i++) {
                float av = As[rg * 4 + i][kk];
                acc[i].x += av * bv.x; acc[i].y += av * bv.y;
                acc[i].z += av * bv.z; acc[i].w += av * bv.w;
            }
        }
        __syncthreads();
    }
    #pragma unroll
    for (int i = 0; i < 4; i++) {
        float4 v = acc[i];
        v.x = fmaxf(v.x, 0.f); v.y = fmaxf(v.y, 0.f);
        v.z = fmaxf(v.z, 0.f); v.w = fmaxf(v.w, 0.f);
        __nv_bfloat162 a = __floats2bfloat162_rn(v.x, v.y);
        __nv_bfloat162 b = __floats2bfloat162_rn(v.z, v.w);
        uint2 o;
        o.x = *reinterpret_cast<uint32_t*>(&a);
        o.y = *reinterpret_cast<uint32_t*>(&b);
        *reinterpret_cast<uint2*>(&Ts[rg * 4 + i][c4 * 4]) = o;
    }
    __syncthreads();

    // ---- phase 2: Out = T @ W2 (T in bf16; unpack via exact shifts) ----
    #pragma unroll
    for (int i = 0; i < 4; i++) acc[i] = make_float4(0.f, 0.f, 0.f, 0.f);
    for (int k0 = 0; k0 < 128; k0 += 16) {
        #pragma unroll
        for (int w = 0; w < 2; w++) {
            int idx = tid + w * 256;
            int kr = idx >> 5, cc = (idx & 31) * 4;
            *reinterpret_cast<float4*>(&Ws[kr][cc]) =
                *reinterpret_cast<const float4*>(W2 + (size_t)(k0 + kr) * 128 + cc);
        }
        __syncthreads();
        #pragma unroll
        for (int kk4 = 0; kk4 < 4; kk4++) {
            float4 bv0 = *reinterpret_cast<const float4*>(&Ws[kk4 * 4 + 0][c4 * 4]);
            float4 bv1 = *reinterpret_cast<const float4*>(&Ws[kk4 * 4 + 1][c4 * 4]);
            float4 bv2 = *reinterpret_cast<const float4*>(&Ws[kk4 * 4 + 2][c4 * 4]);
            float4 bv3 = *reinterpret_cast<const float4*>(&Ws[kk4 * 4 + 3][c4 * 4]);
            #pragma unroll
            for (int i = 0; i < 4; i++) {
                uint2 t = *reinterpret_cast<const uint2*>(&Ts[rg * 4 + i][k0 + kk4 * 4]);
                float f0 = __uint_as_float(t.x << 16);
                float f1 = __uint_as_float(t.x & 0xffff0000u);
                float f2 = __uint_as_float(t.y << 16);
                float f3 = __uint_as_float(t.y & 0xffff0000u);
                acc[i].x += f0 * bv0.x; acc[i].y += f0 * bv0.y;
                acc[i].z += f0 * bv0.z; acc[i].w += f0 * bv0.w;
                acc[i].x += f1 * bv1.x; acc[i].y += f1 * bv1.y;
                acc[i].z += f1 * bv1.z; acc[i].w += f1 * bv1.w;
                acc[i].x += f2 * bv2.x; acc[i].y += f2 * bv2.y;
                acc[i].z += f2 * bv2.z; acc[i].w += f2 * bv2.w;
                acc[i].x += f3 * bv3.x; acc[i].y += f3 * bv3.y;
                acc[i].z += f3 * bv3.z; acc[i].w += f3 * bv3.w;
            }
        }
        __syncthreads();
    }
    #pragma unroll
    for (int i = 0; i < 4; i++) {
        int gr = row0 + rg * 4 + i;
        if (gr < M) {
            float4 v = acc[i];
            __nv_bfloat162 a = __floats2bfloat162_rn(v.x, v.y);
            __nv_bfloat162 b = __floats2bfloat162_rn(v.z, v.w);
            uint2 o;
            o.x = *reinterpret_cast<uint32_t*>(&a);
            o.y = *reinterpret_cast<uint32_t*>(&b);
            *reinterpret_cast<uint2*>(Out + (size_t)gr * 128 + c4 * 4) = o;
        }
    }
}

// ---------------- agg2: v-side warp-per-segment mean, bf16 source, relu+BN, u16 adj ----------------
__global__ void __launch_bounds__(256)
seg_agg2_h128_bn(const __nv_bfloat16* __restrict__ src, const int* __restrict__ cnt,
                 const uint16_t* __restrict__ adj, float* __restrict__ dst, int nseg,
                 const float* __restrict__ bng, const float* __restrict__ bnb,
                 const float* __restrict__ bnm, const float* __restrict__ bnv) {
    const int lane = threadIdx.x & 31;
    const int half = lane >> 4;
    const int sub  = lane & 15;
    const int wid = (blockIdx.x * (blockDim.x >> 5)) + (threadIdx.x >> 5);
    const int nw = gridDim.x * (blockDim.x >> 5);

    float sc[8], sh[8];
    #pragma unroll
    for (int k = 0; k < 8; k++) {
        int c = sub * 8 + k;
        float scv = rsqrtf(bnv[c] + BN_EPS) * bng[c];
        sc[k] = scv;
        sh[k] = bnb[c] - bnm[c] * scv;
    }

    for (int s = wid; s < nseg; s += nw) {
        int deg = cnt[s]; if (deg > VPAD) deg = VPAD;
        const size_t base = (size_t)s << 7;
        float acc[8];
        #pragma unroll
        for (int k = 0; k < 8; k++) acc[k] = 0.f;

        int j = half;
        for (; j + 6 < deg; j += 8) {
            int i0 = adj[base + j],     i1 = adj[base + j + 2];
            int i2 = adj[base + j + 4], i3 = adj[base + j + 6];
            uint4 p0 = *reinterpret_cast<const uint4*>(src + (size_t)i0 * 128 + sub * 8);
            uint4 p1 = *reinterpret_cast<const uint4*>(src + (size_t)i1 * 128 + sub * 8);
            uint4 p2 = *reinterpret_cast<const uint4*>(src + (size_t)i2 * 128 + sub * 8);
            uint4 p3 = *reinterpret_cast<const uint4*>(src + (size_t)i3 * 128 + sub * 8);
            acc_bf16x8(acc, p0);
            acc_bf16x8(acc, p1);
            acc_bf16x8(acc, p2);
            acc_bf16x8(acc, p3);
        }
        for (; j < deg; j += 2) {
            int i0 = adj[base + j];
            uint4 p0 = *reinterpret_cast<const uint4*>(src + (size_t)i0 * 128 + sub * 8);
            acc_bf16x8(acc, p0);
        }
        #pragma unroll
        for (int k = 0; k < 8; k++)
            acc[k] += __shfl_xor_sync(0xffffffffu, acc[k], 16);
        if (half == 0) {
            float inv = 1.0f / (float)(deg < 1 ? 1 : deg);
            float o[8];
            #pragma unroll
            for (int k = 0; k < 8; k++)
                o[k] = fmaxf(acc[k] * inv, 0.f) * sc[k] + sh[k];
            float4 o0 = make_float4(o[0], o[1], o[2], o[3]);
            float4 o1 = make_float4(o[4], o[5], o[6], o[7]);
            *reinterpret_cast<float4*>(dst + (size_t)s * 128 + sub * 8) = o0;
            *reinterpret_cast<float4*>(dst + (size_t)s * 128 + sub * 8 + 4) = o1;
        }
    }
}

// ---------------- layer-2 v2e GEMM: [M,128]@[128,40] -> bf16. 128-row tile, 4x4/thread ----------------
__global__ void __launch_bounds__(320)
gemm40k128(const float* __restrict__ A, const float* __restrict__ W,
           __nv_bfloat16* __restrict__ Out, int M) {
    __shared__ float As[128][20];
    __shared__ __align__(16) float Ws[16][40];
    const int tid = threadIdx.x;
    const int chunk = tid % 10;
    const int rg = tid / 10;
    const int row0 = blockIdx.x * 128;
    float4 acc[4];
    #pragma unroll
    for (int i = 0; i < 4; i++) acc[i] = make_float4(0.f, 0.f, 0.f, 0.f);

    for (int k0 = 0; k0 < 128; k0 += 16) {
        if (tid < 256) {
            int r = tid >> 1, cc = (tid & 1) * 8;
            int gr = row0 + r;
            float4 v0 = make_float4(0.f, 0.f, 0.f, 0.f);
            float4 v1 = make_float4(0.f, 0.f, 0.f, 0.f);
            if (gr < M) {
                v0 = *reinterpret_cast<const float4*>(A + (size_t)gr * 128 + k0 + cc);
                v1 = *reinterpret_cast<const float4*>(A + (size_t)gr * 128 + k0 + cc + 4);
            }
            *reinterpret_cast<float4*>(&As[r][cc])     = v0;
            *reinterpret_cast<float4*>(&As[r][cc + 4]) = v1;
        }
        if (tid < 160) {
            int kr = tid / 10, cc = (tid % 10) * 4;
            *reinterpret_cast<float4*>(&Ws[kr][cc]) =
                *reinterpret_cast<const float4*>(W + (size_t)(k0 + kr) * 40 + cc);
        }
        __syncthreads();
        #pragma unroll
        for (int kk = 0; kk < 16; kk++) {
            float4 bv = *reinterpret_cast<const float4*>(&Ws[kk][chunk * 4]);
            #pragma unroll
            for (int i = 0; i < 4; i++) {
                float av = As[rg * 4 + i][kk];
                acc[i].x += av * bv.x; acc[i].y += av * bv.y;
                acc[i].z += av * bv.z; acc[i].w += av * bv.w;
            }
        }
        __syncthreads();
    }
    #pragma unroll
    for (int i = 0; i < 4; i++) {
        int gr = row0 + rg * 4 + i;
        if (gr < M) {
            float4 v = acc[i];
            __nv_bfloat162 a = __floats2bfloat162_rn(v.x, v.y);
            __nv_bfloat162 b = __floats2bfloat162_rn(v.z, v.w);
            uint2 o;
            o.x = *reinterpret_cast<uint32_t*>(&a);
            o.y = *reinterpret_cast<uint32_t*>(&b);
            *reinterpret_cast<uint2*>(Out + (size_t)gr * 40 + chunk * 4) = o;
        }
    }
}

// ---------------- agg3 FUSED with layer-2 e2v GEMM ----------------
__global__ void __launch_bounds__(120)
seg_agg3_fused(const __nv_bfloat16* __restrict__ src, const int* __restrict__ cnt,
               const int* __restrict__ adj, const float* __restrict__ W,
               __nv_bfloat16* __restrict__ dst, int nseg) {
    const int tid = threadIdx.x;
    const int chunk = tid % 10;
    const int rl = tid / 10;
    __shared__ float sacc[12][10][4];
    __shared__ float srow[40];
    __shared__ float Wsb[40][40];

    for (int i = tid; i < 1600; i += 120) Wsb[i / 40][i % 40] = W[i];
    __syncthreads();

    for (int s = blockIdx.x; s < nseg; s += gridDim.x) {
        int deg = cnt[s]; if (deg > EPAD) deg = EPAD;
        const size_t base = (size_t)s << 8;
        float acc[4] = {0.f, 0.f, 0.f, 0.f};

        int j = rl;
        for (; j + 36 < deg; j += 48) {
            int i0 = adj[base + j],      i1 = adj[base + j + 12];
            int i2 = adj[base + j + 24], i3 = adj[base + j + 36];
            uint2 p0 = *reinterpret_cast<const uint2*>(src + (size_t)i0 * 40 + chunk * 4);
            uint2 p1 = *reinterpret_cast<const uint2*>(src + (size_t)i1 * 40 + chunk * 4);
            uint2 p2 = *reinterpret_cast<const uint2*>(src + (size_t)i2 * 40 + chunk * 4);
            uint2 p3 = *reinterpret_cast<const uint2*>(src + (size_t)i3 * 40 + chunk * 4);
            acc_bf16x4(acc, p0);
            acc_bf16x4(acc, p1);
            acc_bf16x4(acc, p2);
            acc_bf16x4(acc, p3);
        }
        for (; j < deg; j += 12) {
            int i0 = adj[base + j];
            uint2 p0 = *reinterpret_cast<const uint2*>(src + (size_t)i0 * 40 + chunk * 4);
            acc_bf16x4(acc, p0);
        }
        #pragma unroll
        for (int k = 0; k < 4; k++) sacc[rl][chunk][k] = acc[k];
        __syncthreads();
        if (rl == 0) {
            #pragma unroll
            for (int r = 1; r < 12; r++)
                #pragma unroll
                for (int k = 0; k < 4; k++) acc[k] += sacc[r][chunk][k];
            float inv = 1.0f / (float)(deg < 1 ? 1 : deg);
            srow[chunk * 4 + 0] = fmaxf(acc[0] * inv, 0.f);
            srow[chunk * 4 + 1] = fmaxf(acc[1] * inv, 0.f);
            srow[chunk * 4 + 2] = fmaxf(acc[2] * inv, 0.f);
            srow[chunk * 4 + 3] = fmaxf(acc[3] * inv, 0.f);
        }
        __syncthreads();
        if (tid < 40) {
            float o = 0.f;
            #pragma unroll
            for (int c = 0; c < 40; c++) o += srow[c] * Wsb[c][tid];
            dst[(size_t)s * 40 + tid] = __float2bfloat16_rn(o);
        }
        __syncthreads();
    }
}

// ---------------- agg4: v-side warp-per-segment mean + log_softmax, bf16 src, u16 adj ----------------
__global__ void __launch_bounds__(256)
seg_agg4_w40_ls(const __nv_bfloat16* __restrict__ src, const int* __restrict__ cnt,
                const uint16_t* __restrict__ adj, float* __restrict__ dst, int nseg) {
    const int lane = threadIdx.x & 31;
    const int rl = lane / 10;
    const int chunk = lane % 10;
    const bool act = lane < 30;
    const int wid = (blockIdx.x * (blockDim.x >> 5)) + (threadIdx.x >> 5);
    const int nw = gridDim.x * (blockDim.x >> 5);

    for (int s = wid; s < nseg; s += nw) {
        int deg = cnt[s]; if (deg > VPAD) deg = VPAD;
        const size_t base = (size_t)s << 7;
        float acc[4] = {0.f, 0.f, 0.f, 0.f};

        if (act) {
            int j = rl;
            for (; j + 9 < deg; j += 12) {
                int i0 = adj[base + j],     i1 = adj[base + j + 3];
                int i2 = adj[base + j + 6], i3 = adj[base + j + 9];
                uint2 p0 = *reinterpret_cast<const uint2*>(src + (size_t)i0 * 40 + chunk * 4);
                uint2 p1 = *reinterpret_cast<const uint2*>(src + (size_t)i1 * 40 + chunk * 4);
                uint2 p2 = *reinterpret_cast<const uint2*>(src + (size_t)i2 * 40 + chunk * 4);
                uint2 p3 = *reinterpret_cast<const uint2*>(src + (size_t)i3 * 40 + chunk * 4);
                acc_bf16x4(acc, p0);
                acc_bf16x4(acc, p1);
                acc_bf16x4(acc, p2);
                acc_bf16x4(acc, p3);
            }
            for (; j < deg; j += 3) {
                int i0 = adj[base + j];
                uint2 p0 = *reinterpret_cast<const uint2*>(src + (size_t)i0 * 40 + chunk * 4);
                acc_bf16x4(acc, p0);
            }
        }
        #pragma unroll
        for (int k = 0; k < 4; k++)
            acc[k] += __shfl_down_sync(0xffffffffu, acc[k], 10)
                    + __shfl_down_sync(0xffffffffu, acc[k], 20);

        float inv = 1.0f / (float)(deg < 1 ? 1 : deg);
        float v0 = acc[0] * inv, v1 = acc[1] * inv, v2 = acc[2] * inv, v3 = acc[3] * inv;

        float m4 = (lane < 10) ? fmaxf(fmaxf(v0, v1), fmaxf(v2, v3)) : -1e30f;
        #pragma unroll
        for (int d = 8; d >= 1; d >>= 1)
            m4 = fmaxf(m4, __shfl_xor_sync(0xffffffffu, m4, d));
        float s4 = 0.f;
        if (lane < 10)
            s4 = __expf(v0 - m4) + __expf(v1 - m4) + __expf(v2 - m4) + __expf(v3 - m4);
        #pragma unroll
        for (int d = 8; d >= 1; d >>= 1)
            s4 += __shfl_xor_sync(0xffffffffu, s4, d);
        float lse = m4 + logf(s4);

        if (lane < 10) {
            float4 o = make_float4(v0 - lse, v1 - lse, v2 - lse, v3 - lse);
            *reinterpret_cast<float4*>(dst + (size_t)s * 40 + chunk * 4) = o;
        }
    }
}

// ---------------- host ----------------
extern "C" void kernel_launch(void* const* d_in, const int* in_sizes, int n_in,
                              void* d_out, int out_size) {
    const float* x     = (const float*)d_in[0];
    const int*   v_ids = (const int*)  d_in[1];
    const int*   e_ids = (const int*)  d_in[2];
    const float* w1a   = (const float*)d_in[3];
    const float* w1b   = (const float*)d_in[4];
    const float* w2a   = (const float*)d_in[5];
    const float* w2b   = (const float*)d_in[6];
    const float* bng   = (const float*)d_in[7];
    const float* bnb   = (const float*)d_in[8];
    const float* bnm   = (const float*)d_in[9];
    const float* bnv   = (const float*)d_in[10];
    float* out = (float*)d_out;
    const int nnz = in_sizes[1];

    void* p;
    cudaGetSymbolAddress(&p, g_ecnt);   int* ecnt  = (int*)p;
    cudaGetSymbolAddress(&p, g_vcnt);   int* vcnt  = (int*)p;
    cudaGetSymbolAddress(&p, g_eadj);   int* eadj  = (int*)p;
    cudaGetSymbolAddress(&p, g_vadj16); uint16_t* vadj = (uint16_t*)p;
    cudaGetSymbolAddress(&p, g_ebuf);   float* ebuf  = (float*)p;
    cudaGetSymbolAddress(&p, g_vbuf);   float* vbuf  = (float*)p;
    cudaGetSymbolAddress(&p, g_xh);     __nv_bfloat16* xh   = (__nv_bfloat16*)p;
    cudaGetSymbolAddress(&p, g_eh);     __nv_bfloat16* eh   = (__nv_bfloat16*)p;
    cudaGetSymbolAddress(&p, g_vb2h);   __nv_bfloat16* vb2h = (__nv_bfloat16*)p;
    cudaGetSymbolAddress(&p, g_e40h);   __nv_bfloat16* e40h = (__nv_bfloat16*)p;

    // 1: convert x + zero counts (fused)
    cvt_zero<<<(NV * CH / 4 + 255) / 256, 256>>>(x, xh, NV * CH, ecnt, vcnt);
    // 2: padded adjacency build (vadj u16)
    build_padded<<<2048, 256>>>(v_ids, e_ids, ecnt, vcnt, eadj, vadj, nnz);
    // 3: agg1 (e-side mean of x)
    seg_agg_h128<<<NE, 128>>>(xh, ecnt, eadj, ebuf, NE);
    // 4: fused layer-1 GEMM pair  <- profiled launch (32-row tiles, grid 625)
    gemm128_fused<<<(NE + 31) / 32, 256>>>(ebuf, w1a, w1b, eh, NE);
    // 5: agg2 (v-side mean + relu + BN), u16 adj
    seg_agg2_h128_bn<<<(NV + 7) / 8, 256>>>(eh, vcnt, vadj, vbuf, NV, bng, bnb, bnm, bnv);
    // 6: layer-2 v2e GEMM -> bf16 (4x4 per thread)
    gemm40k128<<<(NV + 127) / 128, 320>>>(vbuf, w2a, vb2h, NV);
    // 7: agg3 fused with e2v GEMM (mean+relu then @W2b -> bf16), 40-thread tail
    seg_agg3_fused<<<2048, 120>>>(vb2h, ecnt, eadj, w2b, e40h, NE);
    // 8: agg4 (v-side mean + log_softmax), u16 adj
    seg_agg4_w40_ls<<<(NV + 7) / 8, 256>>>(e40h, vcnt, vadj, out, NV);
}

// round 17
// speedup vs baseline: 1.0168x; 1.0168x over previous
#include <cuda_runtime.h>
#include <cuda_bf16.h>
#include <math.h>
#include <stdint.h>

#define NV 100000
#define NE 20000
#define CH 128
#define NCLS 40
#define BN_EPS 1e-5f
#define EPAD 256   // max hyperedge degree slot (mean 160, sigma 12.6)
#define VPAD 128   // max vertex degree slot (mean 32, sigma 5.7)

// ---------------- scratch (device globals; no cudaMalloc allowed) ----------------
__device__ static float g_ebuf [(size_t)NE * CH];           // 10.24 MB (agg1 out)
__device__ static __nv_bfloat16 g_vh   [(size_t)NV * CH];   // 25.6 MB (agg2 out bf16 -> gemm40 src)
__device__ static __nv_bfloat16 g_xh   [(size_t)NV * CH];   // 25.6 MB (x bf16)
__device__ static __nv_bfloat16 g_eh   [(size_t)NE * CH];   // 5.12 MB (fused gemm out -> agg2 src)
__device__ static __nv_bfloat16 g_vb2h [(size_t)NV * NCLS]; // 8 MB (gemm40 out -> agg3 src)
__device__ static __nv_bfloat16 g_e40h [(size_t)NE * NCLS]; // 1.6 MB (fused agg3 out -> agg4 src)
__device__ static int      g_ecnt[NE];
__device__ static int      g_vcnt[NV];
__device__ static int      g_eadj[(size_t)NE * EPAD];       // 20.48 MB (v ids, 32-bit)
__device__ static uint16_t g_vadj16[(size_t)NV * VPAD];     // 25.6 MB (e ids < 20000 -> u16)

// ---------------- prelude: x->bf16 convert fused with count zeroing ----------------
__global__ void cvt_zero(const float* __restrict__ src, __nv_bfloat16* __restrict__ dst, int n,
                         int* ecnt, int* vcnt) {
    int t = blockIdx.x * blockDim.x + threadIdx.x;
    int i = t * 4;
    if (i < n) {
        float4 f = *reinterpret_cast<const float4*>(src + i);
        __nv_bfloat162 a = __floats2bfloat162_rn(f.x, f.y);
        __nv_bfloat162 b = __floats2bfloat162_rn(f.z, f.w);
        uint2 o;
        o.x = *reinterpret_cast<uint32_t*>(&a);
        o.y = *reinterpret_cast<uint32_t*>(&b);
        *reinterpret_cast<uint2*>(dst + i) = o;
    }
    if (t < NE) ecnt[t] = 0;
    int u = t - NE;
    if (u >= 0 && u < NV) vcnt[u] = 0;
}

// Single-pass padded adjacency build (rank = atomic return value). vadj stored u16.
__global__ void build_padded(const int* __restrict__ v_ids, const int* __restrict__ e_ids,
                             int* ecnt, int* vcnt,
                             int* __restrict__ eadj, uint16_t* __restrict__ vadj, int nnz) {
    for (int i = blockIdx.x * blockDim.x + threadIdx.x; i < nnz; i += gridDim.x * blockDim.x) {
        int e = e_ids[i], v = v_ids[i];
        int re = atomicAdd(&ecnt[e], 1);
        if (re < EPAD) eadj[((size_t)e << 8) + re] = v;
        int rv = atomicAdd(&vcnt[v], 1);
        if (rv < VPAD) vadj[((size_t)v << 7) + rv] = (uint16_t)e;
    }
}

// bf16x2 word -> packed f32x2 (exact: bf16->f32 is a left shift by 16)
__device__ __forceinline__ uint64_t bf16x2_to_f32x2(uint32_t w) {
    uint32_t lo = w << 16;
    uint32_t hi = w & 0xffff0000u;
    uint64_t r;
    asm("mov.b64 %0, {%1, %2};" : "=l"(r) : "r"(lo), "r"(hi));
    return r;
}

__device__ __forceinline__ void acc2_bf16x8(uint64_t* acc2, uint4 p) {
    const uint32_t* w = &p.x;
    #pragma unroll
    for (int q = 0; q < 4; q++) {
        uint64_t f2 = bf16x2_to_f32x2(w[q]);
        asm("add.rn.f32x2 %0, %0, %1;" : "+l"(acc2[q]) : "l"(f2));
    }
}

__device__ __forceinline__ void acc_bf16x8(float* acc, uint4 p) {
    const uint32_t* w = &p.x;
    #pragma unroll
    for (int q = 0; q < 4; q++) {
        float2 f = __bfloat1622float2(*reinterpret_cast<const __nv_bfloat162*>(&w[q]));
        acc[q * 2 + 0] += f.x;
        acc[q * 2 + 1] += f.y;
    }
}

__device__ __forceinline__ void acc_bf16x4(float* acc, uint2 p) {
    const uint32_t* w = &p.x;
    #pragma unroll
    for (int q = 0; q < 2; q++) {
        float2 f = __bfloat1622float2(*reinterpret_cast<const __nv_bfloat162*>(&w[q]));
        acc[q * 2 + 0] += f.x;
        acc[q * 2 + 1] += f.y;
    }
}

// ---------------- agg1: e-side segment mean, bf16 source, 128 ch, f32x2 accumulate ----------------
__global__ void __launch_bounds__(128)
seg_agg_h128(const __nv_bfloat16* __restrict__ src, const int* __restrict__ cnt,
             const int* __restrict__ adj, float* __restrict__ dst, int nseg) {
    const int tid = threadIdx.x;
    const int chunk = tid % 16;
    const int rl = tid / 16;
    __shared__ float sacc[8][16][8];

    for (int s = blockIdx.x; s < nseg; s += gridDim.x) {
        int deg = cnt[s]; if (deg > EPAD) deg = EPAD;
        const size_t base = (size_t)s << 8;
        uint64_t acc2[4];
        #pragma unroll
        for (int q = 0; q < 4; q++) acc2[q] = 0ull;

        int j = rl;
        for (; j + 24 < deg; j += 32) {
            int i0 = adj[base + j],      i1 = adj[base + j + 8];
            int i2 = adj[base + j + 16], i3 = adj[base + j + 24];
            uint4 p0 = *reinterpret_cast<const uint4*>(src + (size_t)i0 * 128 + chunk * 8);
            uint4 p1 = *reinterpret_cast<const uint4*>(src + (size_t)i1 * 128 + chunk * 8);
            uint4 p2 = *reinterpret_cast<const uint4*>(src + (size_t)i2 * 128 + chunk * 8);
            uint4 p3 = *reinterpret_cast<const uint4*>(src + (size_t)i3 * 128 + chunk * 8);
            acc2_bf16x8(acc2, p0);
            acc2_bf16x8(acc2, p1);
            acc2_bf16x8(acc2, p2);
            acc2_bf16x8(acc2, p3);
        }
        for (; j < deg; j += 8) {
            int i0 = adj[base + j];
            uint4 p0 = *reinterpret_cast<const uint4*>(src + (size_t)i0 * 128 + chunk * 8);
            acc2_bf16x8(acc2, p0);
        }
        float accf[8];
        #pragma unroll
        for (int q = 0; q < 4; q++) {
            uint32_t lo, hi;
            asm("mov.b64 {%0, %1}, %2;" : "=r"(lo), "=r"(hi) : "l"(acc2[q]));
            accf[q * 2 + 0] = __uint_as_float(lo);
            accf[q * 2 + 1] = __uint_as_float(hi);
        }
        #pragma unroll
        for (int k = 0; k < 8; k++) sacc[rl][chunk][k] = accf[k];
        __syncthreads();
        if (rl == 0) {
            #pragma unroll
            for (int r = 1; r < 8; r++)
                #pragma unroll
                for (int k = 0; k < 8; k++) accf[k] += sacc[r][chunk][k];
            float inv = 1.0f / (float)(deg < 1 ? 1 : deg);
            #pragma unroll
            for (int k = 0; k < 8; k++) accf[k] *= inv;
            float4 o0 = make_float4(accf[0], accf[1], accf[2], accf[3]);
            float4 o1 = make_float4(accf[4], accf[5], accf[6], accf[7]);
            *reinterpret_cast<float4*>(dst + (size_t)s * 128 + chunk * 8) = o0;
            *reinterpret_cast<float4*>(dst + (size_t)s * 128 + chunk * 8 + 4) = o1;
        }
        __syncthreads();
    }
}

// ---------------- fused layer-1 GEMM pair: Out_bf16 = relu(A@W1) @ W2 ----------------
__global__ void __launch_bounds__(256)
gemm128_fused(const float* __restrict__ A, const float* __restrict__ W1,
              const float* __restrict__ W2, __nv_bfloat16* __restrict__ Out, int M) {
    __shared__ float As[32][16];
    __shared__ __align__(16) float Ws[16][128];
    __shared__ __align__(16) __nv_bfloat16 Ts[32][128];
    const int tid = threadIdx.x;
    const int c4 = tid % 32;
    const int rg = tid / 32;
    const int row0 = blockIdx.x * 32;
    float4 acc[4];
    #pragma unroll
    for (int i = 0; i < 4; i++) acc[i] = make_float4(0.f, 0.f, 0.f, 0.f);

    // ---- phase 1: T = relu(A @ W1) ----
    for (int k0 = 0; k0 < 128; k0 += 16) {
        if (tid < 128) {
            int r = tid >> 2, cc = (tid & 3) * 4;
            int gr = row0 + r;
            float4 v = make_float4(0.f, 0.f, 0.f, 0.f);
            if (gr < M) v = *reinterpret_cast<const float4*>(A + (size_t)gr * 128 + k0 + cc);
            *reinterpret_cast<float4*>(&As[r][cc]) = v;
        }
        #pragma unroll
        for (int w = 0; w < 2; w++) {
            int idx = tid + w * 256;
            int kr = idx >> 5, cc = (idx & 31) * 4;
            *reinterpret_cast<float4*>(&Ws[kr][cc]) =
                *reinterpret_cast<const float4*>(W1 + (size_t)(k0 + kr) * 128 + cc);
        }
        __syncthreads();
        #pragma unroll
        for (int kk = 0; kk < 16; kk++) {
            float4 bv = *reinterpret_cast<const float4*>(&Ws[kk][c4 * 4]);
            #pragma unroll
            for (int i = 0; i < 4; i++) {
                float av = As[rg * 4 + i][kk];
                acc[i].x += av * bv.x; acc[i].y += av * bv.y;
                acc[i].z += av * bv.z; acc[i].w += av * bv.w;
            }
        }
        __syncthreads();
    }
    #pragma unroll
    for (int i = 0; i < 4; i++) {
        float4 v = acc[i];
        v.x = fmaxf(v.x, 0.f); v.y = fmaxf(v.y, 0.f);
        v.z = fmaxf(v.z, 0.f); v.w = fmaxf(v.w, 0.f);
        __nv_bfloat162 a = __floats2bfloat162_rn(v.x, v.y);
        __nv_bfloat162 b = __floats2bfloat162_rn(v.z, v.w);
        uint2 o;
        o.x = *reinterpret_cast<uint32_t*>(&a);
        o.y = *reinterpret_cast<uint32_t*>(&b);
        *reinterpret_cast<uint2*>(&Ts[rg * 4 + i][c4 * 4]) = o;
    }
    __syncthreads();

    // ---- phase 2: Out = T @ W2 ----
    #pragma unroll
    for (int i = 0; i < 4; i++) acc[i] = make_float4(0.f, 0.f, 0.f, 0.f);
    for (int k0 = 0; k0 < 128; k0 += 16) {
        #pragma unroll
        for (int w = 0; w < 2; w++) {
            int idx = tid + w * 256;
            int kr = idx >> 5, cc = (idx & 31) * 4;
            *reinterpret_cast<float4*>(&Ws[kr][cc]) =
                *reinterpret_cast<const float4*>(W2 + (size_t)(k0 + kr) * 128 + cc);
        }
        __syncthreads();
        #pragma unroll
        for (int kk4 = 0; kk4 < 4; kk4++) {
            float4 bv0 = *reinterpret_cast<const float4*>(&Ws[kk4 * 4 + 0][c4 * 4]);
            float4 bv1 = *reinterpret_cast<const float4*>(&Ws[kk4 * 4 + 1][c4 * 4]);
            float4 bv2 = *reinterpret_cast<const float4*>(&Ws[kk4 * 4 + 2][c4 * 4]);
            float4 bv3 = *reinterpret_cast<const float4*>(&Ws[kk4 * 4 + 3][c4 * 4]);
            #pragma unroll
            for (int i = 0; i < 4; i++) {
                uint2 t = *reinterpret_cast<const uint2*>(&Ts[rg * 4 + i][k0 + kk4 * 4]);
                float f0 = __uint_as_float(t.x << 16);
                float f1 = __uint_as_float(t.x & 0xffff0000u);
                float f2 = __uint_as_float(t.y << 16);
                float f3 = __uint_as_float(t.y & 0xffff0000u);
                acc[i].x += f0 * bv0.x; acc[i].y += f0 * bv0.y;
                acc[i].z += f0 * bv0.z; acc[i].w += f0 * bv0.w;
                acc[i].x += f1 * bv1.x; acc[i].y += f1 * bv1.y;
                acc[i].z += f1 * bv1.z; acc[i].w += f1 * bv1.w;
                acc[i].x += f2 * bv2.x; acc[i].y += f2 * bv2.y;
                acc[i].z += f2 * bv2.z; acc[i].w += f2 * bv2.w;
                acc[i].x += f3 * bv3.x; acc[i].y += f3 * bv3.y;
                acc[i].z += f3 * bv3.z; acc[i].w += f3 * bv3.w;
            }
        }
        __syncthreads();
    }
    #pragma unroll
    for (int i = 0; i < 4; i++) {
        int gr = row0 + rg * 4 + i;
        if (gr < M) {
            float4 v = acc[i];
            __nv_bfloat162 a = __floats2bfloat162_rn(v.x, v.y);
            __nv_bfloat162 b = __floats2bfloat162_rn(v.z, v.w);
            uint2 o;
            o.x = *reinterpret_cast<uint32_t*>(&a);
            o.y = *reinterpret_cast<uint32_t*>(&b);
            *reinterpret_cast<uint2*>(Out + (size_t)gr * 128 + c4 * 4) = o;
        }
    }
}

// ---------------- agg2: v-side warp-per-segment mean, bf16 src, relu+BN, bf16 OUT ----------------
__global__ void __launch_bounds__(256)
seg_agg2_h128_bn(const __nv_bfloat16* __restrict__ src, const int* __restrict__ cnt,
                 const uint16_t* __restrict__ adj, __nv_bfloat16* __restrict__ dst, int nseg,
                 const float* __restrict__ bng, const float* __restrict__ bnb,
                 const float* __restrict__ bnm, const float* __restrict__ bnv) {
    const int lane = threadIdx.x & 31;
    const int half = lane >> 4;
    const int sub  = lane & 15;
    const int wid = (blockIdx.x * (blockDim.x >> 5)) + (threadIdx.x >> 5);
    const int nw = gridDim.x * (blockDim.x >> 5);

    float sc[8], sh[8];
    #pragma unroll
    for (int k = 0; k < 8; k++) {
        int c = sub * 8 + k;
        float scv = rsqrtf(bnv[c] + BN_EPS) * bng[c];
        sc[k] = scv;
        sh[k] = bnb[c] - bnm[c] * scv;
    }

    for (int s = wid; s < nseg; s += nw) {
        int deg = cnt[s]; if (deg > VPAD) deg = VPAD;
        const size_t base = (size_t)s << 7;
        float acc[8];
        #pragma unroll
        for (int k = 0; k < 8; k++) acc[k] = 0.f;

        int j = half;
        for (; j + 6 < deg; j += 8) {
            int i0 = adj[base + j],     i1 = adj[base + j + 2];
            int i2 = adj[base + j + 4], i3 = adj[base + j + 6];
            uint4 p0 = *reinterpret_cast<const uint4*>(src + (size_t)i0 * 128 + sub * 8);
            uint4 p1 = *reinterpret_cast<const uint4*>(src + (size_t)i1 * 128 + sub * 8);
            uint4 p2 = *reinterpret_cast<const uint4*>(src + (size_t)i2 * 128 + sub * 8);
            uint4 p3 = *reinterpret_cast<const uint4*>(src + (size_t)i3 * 128 + sub * 8);
            acc_bf16x8(acc, p0);
            acc_bf16x8(acc, p1);
            acc_bf16x8(acc, p2);
            acc_bf16x8(acc, p3);
        }
        for (; j < deg; j += 2) {
            int i0 = adj[base + j];
            uint4 p0 = *reinterpret_cast<const uint4*>(src + (size_t)i0 * 128 + sub * 8);
            acc_bf16x8(acc, p0);
        }
        #pragma unroll
        for (int k = 0; k < 8; k++)
            acc[k] += __shfl_xor_sync(0xffffffffu, acc[k], 16);
        if (half == 0) {
            float inv = 1.0f / (float)(deg < 1 ? 1 : deg);
            float o[8];
            #pragma unroll
            for (int k = 0; k < 8; k++)
                o[k] = fmaxf(acc[k] * inv, 0.f) * sc[k] + sh[k];
            __nv_bfloat162 b0 = __floats2bfloat162_rn(o[0], o[1]);
            __nv_bfloat162 b1 = __floats2bfloat162_rn(o[2], o[3]);
            __nv_bfloat162 b2 = __floats2bfloat162_rn(o[4], o[5]);
            __nv_bfloat162 b3 = __floats2bfloat162_rn(o[6], o[7]);
            uint4 ob;
            ob.x = *reinterpret_cast<uint32_t*>(&b0);
            ob.y = *reinterpret_cast<uint32_t*>(&b1);
            ob.z = *reinterpret_cast<uint32_t*>(&b2);
            ob.w = *reinterpret_cast<uint32_t*>(&b3);
            *reinterpret_cast<uint4*>(dst + (size_t)s * 128 + sub * 8) = ob;
        }
    }
}

// ---------------- layer-2 v2e GEMM: bf16[M,128]@[128,40] -> bf16. 128-row tile, 4x4/thread ----------------
__global__ void __launch_bounds__(320)
gemm40k128(const __nv_bfloat16* __restrict__ A, const float* __restrict__ W,
           __nv_bfloat16* __restrict__ Out, int M) {
    __shared__ float As[128][20];
    __shared__ __align__(16) float Ws[16][40];
    const int tid = threadIdx.x;
    const int chunk = tid % 10;
    const int rg = tid / 10;
    const int row0 = blockIdx.x * 128;
    float4 acc[4];
    #pragma unroll
    for (int i = 0; i < 4; i++) acc[i] = make_float4(0.f, 0.f, 0.f, 0.f);

    for (int k0 = 0; k0 < 128; k0 += 16) {
        if (tid < 256) {
            int r = tid >> 1, cc = (tid & 1) * 8;
            int gr = row0 + r;
            uint4 p = make_uint4(0u, 0u, 0u, 0u);
            if (gr < M)
                p = *reinterpret_cast<const uint4*>(A + (size_t)gr * 128 + k0 + cc);
            // exact bf16 -> f32 unpack via shifts
            float f0 = __uint_as_float(p.x << 16), f1 = __uint_as_float(p.x & 0xffff0000u);
            float f2 = __uint_as_float(p.y << 16), f3 = __uint_as_float(p.y & 0xffff0000u);
            float f4 = __uint_as_float(p.z << 16), f5 = __uint_as_float(p.z & 0xffff0000u);
            float f6 = __uint_as_float(p.w << 16), f7 = __uint_as_float(p.w & 0xffff0000u);
            *reinterpret_cast<float4*>(&As[r][cc])     = make_float4(f0, f1, f2, f3);
            *reinterpret_cast<float4*>(&As[r][cc + 4]) = make_float4(f4, f5, f6, f7);
        }
        if (tid < 160) {
            int kr = tid / 10, cc = (tid % 10) * 4;
            *reinterpret_cast<float4*>(&Ws[kr][cc]) =
                *reinterpret_cast<const float4*>(W + (size_t)(k0 + kr) * 40 + cc);
        }
        __syncthreads();
        #pragma unroll
        for (int kk = 0; kk < 16; kk++) {
            float4 bv = *reinterpret_cast<const float4*>(&Ws[kk][chunk * 4]);
            #pragma unroll
            for (int i = 0; i < 4; i++) {
                float av = As[rg * 4 + i][kk];
                acc[i].x += av * bv.x; acc[i].y += av * bv.y;
                acc[i].z += av * bv.z; acc[i].w += av * bv.w;
            }
        }
        __syncthreads();
    }
    #pragma unroll
    for (int i = 0; i < 4; i++) {
        int gr = row0 + rg * 4 + i;
        if (gr < M) {
            float4 v = acc[i];
            __nv_bfloat162 a = __floats2bfloat162_rn(v.x, v.y);
            __nv_bfloat162 b = __floats2bfloat162_rn(v.z, v.w);
            uint2 o;
            o.x = *reinterpret_cast<uint32_t*>(&a);
            o.y = *reinterpret_cast<uint32_t*>(&b);
            *reinterpret_cast<uint2*>(Out + (size_t)gr * 40 + chunk * 4) = o;
        }
    }
}

// ---------------- agg3 FUSED with layer-2 e2v GEMM ----------------
__global__ void __launch_bounds__(120)
seg_agg3_fused(const __nv_bfloat16* __restrict__ src, const int* __restrict__ cnt,
               const int* __restrict__ adj, const float* __restrict__ W,
               __nv_bfloat16* __restrict__ dst, int nseg) {
    const int tid = threadIdx.x;
    const int chunk = tid % 10;
    const int rl = tid / 10;
    __shared__ float sacc[12][10][4];
    __shared__ float srow[40];
    __shared__ float Wsb[40][40];

    for (int i = tid; i < 1600; i += 120) Wsb[i / 40][i % 40] = W[i];
    __syncthreads();

    for (int s = blockIdx.x; s < nseg; s += gridDim.x) {
        int deg = cnt[s]; if (deg > EPAD) deg = EPAD;
        const size_t base = (size_t)s << 8;
        float acc[4] = {0.f, 0.f, 0.f, 0.f};

        int j = rl;
        for (; j + 36 < deg; j += 48) {
            int i0 = adj[base + j],      i1 = adj[base + j + 12];
            int i2 = adj[base + j + 24], i3 = adj[base + j + 36];
            uint2 p0 = *reinterpret_cast<const uint2*>(src + (size_t)i0 * 40 + chunk * 4);
            uint2 p1 = *reinterpret_cast<const uint2*>(src + (size_t)i1 * 40 + chunk * 4);
            uint2 p2 = *reinterpret_cast<const uint2*>(src + (size_t)i2 * 40 + chunk * 4);
            uint2 p3 = *reinterpret_cast<const uint2*>(src + (size_t)i3 * 40 + chunk * 4);
            acc_bf16x4(acc, p0);
            acc_bf16x4(acc, p1);
            acc_bf16x4(acc, p2);
            acc_bf16x4(acc, p3);
        }
        for (; j < deg; j += 12) {
            int i0 = adj[base + j];
            uint2 p0 = *reinterpret_cast<const uint2*>(src + (size_t)i0 * 40 + chunk * 4);
            acc_bf16x4(acc, p0);
        }
        #pragma unroll
        for (int k = 0; k < 4; k++) sacc[rl][chunk][k] = acc[k];
        __syncthreads();
        if (rl == 0) {
            #pragma unroll
            for (int r = 1; r < 12; r++)
                #pragma unroll
                for (int k = 0; k < 4; k++) acc[k] += sacc[r][chunk][k];
            float inv = 1.0f / (float)(deg < 1 ? 1 : deg);
            srow[chunk * 4 + 0] = fmaxf(acc[0] * inv, 0.f);
            srow[chunk * 4 + 1] = fmaxf(acc[1] * inv, 0.f);
            srow[chunk * 4 + 2] = fmaxf(acc[2] * inv, 0.f);
            srow[chunk * 4 + 3] = fmaxf(acc[3] * inv, 0.f);
        }
        __syncthreads();
        if (tid < 40) {
            float o = 0.f;
            #pragma unroll
            for (int c = 0; c < 40; c++) o += srow[c] * Wsb[c][tid];
            dst[(size_t)s * 40 + tid] = __float2bfloat16_rn(o);
        }
        __syncthreads();
    }
}

// ---------------- agg4: v-side warp-per-segment mean + log_softmax, bf16 src, u16 adj ----------------
__global__ void __launch_bounds__(256)
seg_agg4_w40_ls(const __nv_bfloat16* __restrict__ src, const int* __restrict__ cnt,
                const uint16_t* __restrict__ adj, float* __restrict__ dst, int nseg) {
    const int lane = threadIdx.x & 31;
    const int rl = lane / 10;
    const int chunk = lane % 10;
    const bool act = lane < 30;
    const int wid = (blockIdx.x * (blockDim.x >> 5)) + (threadIdx.x >> 5);
    const int nw = gridDim.x * (blockDim.x >> 5);

    for (int s = wid; s < nseg; s += nw) {
        int deg = cnt[s]; if (deg > VPAD) deg = VPAD;
        const size_t base = (size_t)s << 7;
        float acc[4] = {0.f, 0.f, 0.f, 0.f};

        if (act) {
            int j = rl;
            for (; j + 9 < deg; j += 12) {
                int i0 = adj[base + j],     i1 = adj[base + j + 3];
                int i2 = adj[base + j + 6], i3 = adj[base + j + 9];
                uint2 p0 = *reinterpret_cast<const uint2*>(src + (size_t)i0 * 40 + chunk * 4);
                uint2 p1 = *reinterpret_cast<const uint2*>(src + (size_t)i1 * 40 + chunk * 4);
                uint2 p2 = *reinterpret_cast<const uint2*>(src + (size_t)i2 * 40 + chunk * 4);
                uint2 p3 = *reinterpret_cast<const uint2*>(src + (size_t)i3 * 40 + chunk * 4);
                acc_bf16x4(acc, p0);
                acc_bf16x4(acc, p1);
                acc_bf16x4(acc, p2);
                acc_bf16x4(acc, p3);
            }
            for (; j < deg; j += 3) {
                int i0 = adj[base + j];
                uint2 p0 = *reinterpret_cast<const uint2*>(src + (size_t)i0 * 40 + chunk * 4);
                acc_bf16x4(acc, p0);
            }
        }
        #pragma unroll
        for (int k = 0; k < 4; k++)
            acc[k] += __shfl_down_sync(0xffffffffu, acc[k], 10)
                    + __shfl_down_sync(0xffffffffu, acc[k], 20);

        float inv = 1.0f / (float)(deg < 1 ? 1 : deg);
        float v0 = acc[0] * inv, v1 = acc[1] * inv, v2 = acc[2] * inv, v3 = acc[3] * inv;

        float m4 = (lane < 10) ? fmaxf(fmaxf(v0, v1), fmaxf(v2, v3)) : -1e30f;
        #pragma unroll
        for (int d = 8; d >= 1; d >>= 1)
            m4 = fmaxf(m4, __shfl_xor_sync(0xffffffffu, m4, d));
        float s4 = 0.f;
        if (lane < 10)
            s4 = __expf(v0 - m4) + __expf(v1 - m4) + __expf(v2 - m4) + __expf(v3 - m4);
        #pragma unroll
        for (int d = 8; d >= 1; d >>= 1)
            s4 += __shfl_xor_sync(0xffffffffu, s4, d);
        float lse = m4 + logf(s4);

        if (lane < 10) {
            float4 o = make_float4(v0 - lse, v1 - lse, v2 - lse, v3 - lse);
            *reinterpret_cast<float4*>(dst + (size_t)s * 40 + chunk * 4) = o;
        }
    }
}

// ---------------- host ----------------
extern "C" void kernel_launch(void* const* d_in, const int* in_sizes, int n_in,
                              void* d_out, int out_size) {
    const float* x     = (const float*)d_in[0];
    const int*   v_ids = (const int*)  d_in[1];
    const int*   e_ids = (const int*)  d_in[2];
    const float* w1a   = (const float*)d_in[3];
    const float* w1b   = (const float*)d_in[4];
    const float* w2a   = (const float*)d_in[5];
    const float* w2b   = (const float*)d_in[6];
    const float* bng   = (const float*)d_in[7];
    const float* bnb   = (const float*)d_in[8];
    const float* bnm   = (const float*)d_in[9];
    const float* bnv   = (const float*)d_in[10];
    float* out = (float*)d_out;
    const int nnz = in_sizes[1];

    void* p;
    cudaGetSymbolAddress(&p, g_ecnt);   int* ecnt  = (int*)p;
    cudaGetSymbolAddress(&p, g_vcnt);   int* vcnt  = (int*)p;
    cudaGetSymbolAddress(&p, g_eadj);   int* eadj  = (int*)p;
    cudaGetSymbolAddress(&p, g_vadj16); uint16_t* vadj = (uint16_t*)p;
    cudaGetSymbolAddress(&p, g_ebuf);   float* ebuf  = (float*)p;
    cudaGetSymbolAddress(&p, g_vh);     __nv_bfloat16* vh   = (__nv_bfloat16*)p;
    cudaGetSymbolAddress(&p, g_xh);     __nv_bfloat16* xh   = (__nv_bfloat16*)p;
    cudaGetSymbolAddress(&p, g_eh);     __nv_bfloat16* eh   = (__nv_bfloat16*)p;
    cudaGetSymbolAddress(&p, g_vb2h);   __nv_bfloat16* vb2h = (__nv_bfloat16*)p;
    cudaGetSymbolAddress(&p, g_e40h);   __nv_bfloat16* e40h = (__nv_bfloat16*)p;

    // 1: convert x + zero counts (fused)
    cvt_zero<<<(NV * CH / 4 + 255) / 256, 256>>>(x, xh, NV * CH, ecnt, vcnt);
    // 2: padded adjacency build (vadj u16)
    build_padded<<<2048, 256>>>(v_ids, e_ids, ecnt, vcnt, eadj, vadj, nnz);
    // 3: agg1 (e-side mean of x)
    seg_agg_h128<<<NE, 128>>>(xh, ecnt, eadj, ebuf, NE);
    // 4: fused layer-1 GEMM pair  <- profiled launch
    gemm128_fused<<<(NE + 31) / 32, 256>>>(ebuf, w1a, w1b, eh, NE);
    // 5: agg2 (v-side mean + relu + BN) -> bf16
    seg_agg2_h128_bn<<<(NV + 7) / 8, 256>>>(eh, vcnt, vadj, vh, NV, bng, bnb, bnm, bnv);
    // 6: layer-2 v2e GEMM, bf16 A -> bf16 out
    gemm40k128<<<(NV + 127) / 128, 320>>>(vh, w2a, vb2h, NV);
    // 7: agg3 fused with e2v GEMM (mean+relu then @W2b -> bf16)
    seg_agg3_fused<<<2048, 120>>>(vb2h, ecnt, eadj, w2b, e40h, NE);
    // 8: agg4 (v-side mean + log_softmax)
    seg_agg4_w40_ls<<<(NV + 7) / 8, 256>>>(e40h, vcnt, vadj, out, NV);
}